// round 14
// baseline (speedup 1.0000x reference)
#include <cuda_runtime.h>
#include <cuda_fp16.h>
#include <cstdint>

#define BATCH 8
#define RESO 64
#define DIMC 256
#define NH 8
#define HD 32
#define WIN 512
#define NWTOT 64
#define LTOK 4096
#define MROWS (NWTOT * WIN)          // 32768
#define PLANE ((size_t)MROWS * 40)   // halves per chunk-plane of g_xh

// ---------------------------------------------------------------------------
// Scratch (__device__ globals: allocation-free rule)
// ---------------------------------------------------------------------------
__device__ __align__(16) __half g_xh[(size_t)NH * PLANE];    // [chunk(=head)][row][40]
__device__ __align__(16) __half g_wh[(size_t)8 * DIMC * 40]; // [chunk][col][40]

// ---------------------------------------------------------------------------
// Helpers
// ---------------------------------------------------------------------------
__device__ __forceinline__ uint32_t packh2(float x, float y) {
    __half2 h = __floats2half2_rn(x, y);
    return *reinterpret_cast<uint32_t*>(&h);
}
__device__ __forceinline__ uint32_t smem_u32(const void* p) {
    uint32_t a;
    asm("{ .reg .u64 t; cvta.to.shared.u64 t, %1; cvt.u32.u64 %0, t; }"
        : "=r"(a) : "l"(p));
    return a;
}
__device__ __forceinline__ void mma16816(float d[4], const uint32_t a[4],
                                         const uint32_t b[2]) {
    asm volatile(
        "mma.sync.aligned.m16n8k16.row.col.f32.f16.f16.f32 "
        "{%0,%1,%2,%3}, {%4,%5,%6,%7}, {%8,%9}, {%0,%1,%2,%3};\n"
        : "+f"(d[0]), "+f"(d[1]), "+f"(d[2]), "+f"(d[3])
        : "r"(a[0]), "r"(a[1]), "r"(a[2]), "r"(a[3]), "r"(b[0]), "r"(b[1]));
}
__device__ __forceinline__ void mma16816_f16(uint32_t d[2], const uint32_t a[4],
                                             const uint32_t b[2]) {
    asm volatile(
        "mma.sync.aligned.m16n8k16.row.col.f16.f16.f16.f16 "
        "{%0,%1}, {%2,%3,%4,%5}, {%6,%7}, {%0,%1};\n"
        : "+r"(d[0]), "+r"(d[1])
        : "r"(a[0]), "r"(a[1]), "r"(a[2]), "r"(a[3]), "r"(b[0]), "r"(b[1]));
}
#define LDSM_X4(r0, r1, r2, r3, addr) \
    asm volatile("ldmatrix.sync.aligned.m8n8.x4.shared.b16 {%0,%1,%2,%3}, [%4];" \
                 : "=r"(r0), "=r"(r1), "=r"(r2), "=r"(r3) : "r"(addr))
#define LDSM_X4_T(r0, r1, r2, r3, addr) \
    asm volatile("ldmatrix.sync.aligned.m8n8.x4.trans.shared.b16 {%0,%1,%2,%3}, [%4];" \
                 : "=r"(r0), "=r"(r1), "=r"(r2), "=r"(r3) : "r"(addr))
#define EX2F16X2(d, s) \
    asm("ex2.approx.f16x2 %0, %1;" : "=r"(d) : "r"(s))
#define CP_ASYNC16(dst, src) \
    asm volatile("cp.async.cg.shared.global [%0], [%1], 16;" :: "r"(dst), "l"(src))
#define CP_COMMIT() asm volatile("cp.async.commit_group;")

// ---------------------------------------------------------------------------
// HMMA flash attention + fused LePE + fused W-preconvert.
// CTA = (window, head): 512 CTAs x 512 threads (16 warps x 32 query rows).
// K and V loaded+converted ONCE per window-head. V fragments via ldmatrix.trans.
// After the MMA loop the dead K region holds the LePE conv output [512][40].
// First-wave CTAs (blockIdx.y==0) also convert W fp32->fp16 for proj.
// smem: K [512][40] + V [512][40] = 80 KB -> 1 CTA/SM (16 warps).
// ---------------------------------------------------------------------------
#define VOFFH (512 * 40)           // halves
#define VOFFB (512 * 40 * 2)       // bytes (40960)
#define ATTN_SMEM_BYTES (2 * 512 * 40 * 2)   // 81920

__global__ __launch_bounds__(512, 1) void attn_hmma(const float* __restrict__ qkv,
                                                    const float* __restrict__ scale_p,
                                                    const float* __restrict__ cw,
                                                    const float* __restrict__ cb,
                                                    const float* __restrict__ W) {
    extern __shared__ __half sm[];
    const int tid = threadIdx.x;
    const int w = blockIdx.x, n = blockIdx.y;
    const int b = w >> 3, j = w & 7;
    const float qscale = scale_p[0] * 1.44269504f;
    const float* kp = qkv + (size_t)BATCH * LTOK * DIMC;
    const float* vp = kp + (size_t)BATCH * LTOK * DIMC;

    // ---- fused prep_w: first-wave CTAs convert W (8192 items over 64 CTAs)
    if (n == 0 && tid < 128) {
        const int gid = w * 128 + tid;              // 0..8191
        const int c = gid >> 5, k0 = (gid & 31) * 8;
        float4 w0 = *(const float4*)&W[(size_t)c * DIMC + k0];
        float4 w1 = *(const float4*)&W[(size_t)c * DIMC + k0 + 4];
        union { uint4 u; __half2 h[4]; } pk;
        pk.h[0] = __floats2half2_rn(w0.x, w0.y);
        pk.h[1] = __floats2half2_rn(w0.z, w0.w);
        pk.h[2] = __floats2half2_rn(w1.x, w1.y);
        pk.h[3] = __floats2half2_rn(w1.z, w1.w);
        *(uint4*)(g_wh + (size_t)(k0 >> 5) * (DIMC * 40) + c * 40 + (k0 & 31)) = pk.u;
    }

    // ---- fill K & V (convert fp32->fp16), layout [key][40] ----
    #pragma unroll
    for (int it = 0; it < 8; it++) {
        int i = tid + it * 512;
        int s = i >> 3, f4 = i & 7;
        int rs = s >> 3, cs = s & 7;
        size_t gbase = ((size_t)b * LTOK + rs * RESO + j * 8 + cs) * DIMC + n * HD + f4 * 4;
        float4 kf = *(const float4*)(kp + gbase);
        float4 vf = *(const float4*)(vp + gbase);
        uint2 hk, hv;
        hk.x = packh2(kf.x, kf.y); hk.y = packh2(kf.z, kf.w);
        hv.x = packh2(vf.x, vf.y); hv.y = packh2(vf.z, vf.w);
        *(uint2*)(sm + s * 40 + f4 * 4)         = hk;
        *(uint2*)(sm + VOFFH + s * 40 + f4 * 4) = hv;
    }

    const int wid = tid >> 5, lane = tid & 31;
    const int g = lane >> 2, t2 = (lane & 3) * 2;
    const int m0 = wid * 32;
    const bool mzero = (j == 7) && ((g < 4) != ((lane & 3) < 2));

    // ---- persistent Q fragments (2 m-tiles, fp16, scaled) ----
    uint32_t qh[2][2][4];
    #pragma unroll
    for (int mt = 0; mt < 2; mt++) {
        #pragma unroll
        for (int rh = 0; rh < 2; rh++) {
            int row = m0 + mt * 16 + g + rh * 8;
            int rs = row >> 3, cs = row & 7;
            const float* src = qkv + ((size_t)b * LTOK + rs * RESO + j * 8 + cs) * DIMC + n * HD;
            #pragma unroll
            for (int ks = 0; ks < 2; ks++) {
                #pragma unroll
                for (int ch = 0; ch < 2; ch++) {
                    float2 f = *(const float2*)(src + ks * 16 + ch * 8 + t2);
                    qh[mt][ks][rh + ch * 2] = packh2(f.x * qscale, f.y * qscale);
                }
            }
        }
    }
    __syncthreads();

    const uint32_t sb = smem_u32(sm);
    const uint32_t kconst = sb + (uint32_t)((lane & 7) * 80 + (lane >> 3) * 16);
    const uint32_t vconst = sb + VOFFB + (uint32_t)((lane & 15) * 80 + (lane >> 4) * 16);

    float O[2][4][4];
    float lsl[2] = {0.f, 0.f}, lsh[2] = {0.f, 0.f};
    #pragma unroll
    for (int mt = 0; mt < 2; mt++)
        #pragma unroll
        for (int nt = 0; nt < 4; nt++)
            #pragma unroll
            for (int e = 0; e < 4; e++) O[mt][nt][e] = 0.f;

    // fp16x2 QK accumulators; after in-place ex2 these ARE the PV A-fragments.
    uint32_t S16[2][2][2][2];
    uint32_t kb[2][2][2];

    // ---- prologue: kb(0), QK(0) -> S16[0] ----
    LDSM_X4(kb[0][0][0], kb[0][0][1], kb[0][1][0], kb[0][1][1], kconst);
    LDSM_X4(kb[1][0][0], kb[1][0][1], kb[1][1][0], kb[1][1][1], kconst + 640u);
    #pragma unroll
    for (int mt = 0; mt < 2; mt++)
        #pragma unroll
        for (int nt = 0; nt < 2; nt++) {
            S16[0][mt][nt][0] = 0u; S16[0][mt][nt][1] = 0u;
            #pragma unroll
            for (int ks = 0; ks < 2; ks++)
                mma16816_f16(S16[0][mt][nt], qh[mt][ks], kb[nt][ks]);
        }

    #pragma unroll 2
    for (int step = 0; step < 32; step++) {
        const int cur = step & 1, nb = cur ^ 1;
        if (step < 31) {
            LDSM_X4(kb[0][0][0], kb[0][0][1], kb[0][1][0], kb[0][1][1],
                    kconst + (uint32_t)(step + 1) * 1280u);
            LDSM_X4(kb[1][0][0], kb[1][0][1], kb[1][1][0], kb[1][1][1],
                    kconst + (uint32_t)(step + 1) * 1280u + 640u);
        }
        // V fragments for step via ldmatrix.trans (V is [key][40])
        uint32_t vb[4][2];
        LDSM_X4_T(vb[0][0], vb[0][1], vb[1][0], vb[1][1],
                  vconst + (uint32_t)step * 1280u);
        LDSM_X4_T(vb[2][0], vb[2][1], vb[3][0], vb[3][1],
                  vconst + (uint32_t)step * 1280u + 32u);

        // ---- softmax: in-place ex2 on fp16 S; lsum via HADD2 + fp32 ----
        #pragma unroll
        for (int mt = 0; mt < 2; mt++) {
            #pragma unroll
            for (int nt = 0; nt < 2; nt++) {
                uint32_t p0, p1;
                EX2F16X2(p0, S16[cur][mt][nt][0]);
                EX2F16X2(p1, S16[cur][mt][nt][1]);
                S16[cur][mt][nt][0] = mzero ? 0u : p0;
                S16[cur][mt][nt][1] = mzero ? 0u : p1;
            }
            __half2 tl = __hadd2(*(__half2*)&S16[cur][mt][0][0],
                                 *(__half2*)&S16[cur][mt][1][0]);
            __half2 th = __hadd2(*(__half2*)&S16[cur][mt][0][1],
                                 *(__half2*)&S16[cur][mt][1][1]);
            float2 fl = __half22float2(tl);
            float2 fh = __half22float2(th);
            lsl[mt] += fl.x + fl.y;
            lsh[mt] += fh.x + fh.y;
        }

        // ---- QK(step+1) overlaps the ex2->PV chain ----
        if (step < 31) {
            #pragma unroll
            for (int mt = 0; mt < 2; mt++)
                #pragma unroll
                for (int nt = 0; nt < 2; nt++) {
                    S16[nb][mt][nt][0] = 0u; S16[nb][mt][nt][1] = 0u;
                    #pragma unroll
                    for (int ks = 0; ks < 2; ks++)
                        mma16816_f16(S16[nb][mt][nt], qh[mt][ks], kb[nt][ks]);
                }
        }

        // ---- PV(step) ----
        #pragma unroll
        for (int mt = 0; mt < 2; mt++)
            #pragma unroll
            for (int ntd = 0; ntd < 4; ntd++)
                mma16816(O[mt][ntd], &S16[cur][mt][0][0], vb[ntd]);
    }

    // ---- quad reduction of row sums ----
    #pragma unroll
    for (int mt = 0; mt < 2; mt++) {
        lsl[mt] += __shfl_xor_sync(0xffffffffu, lsl[mt], 1);
        lsl[mt] += __shfl_xor_sync(0xffffffffu, lsl[mt], 2);
        lsh[mt] += __shfl_xor_sync(0xffffffffu, lsh[mt], 1);
        lsh[mt] += __shfl_xor_sync(0xffffffffu, lsh[mt], 2);
    }

    // ---- fused LePE conv: K region is dead; write lepe [512 tok][40] there.
    // Warp wid covers tokens wid*32..wid*32+31 (image rows wid*4..wid*4+3).
    __syncthreads();     // all K reads done before overwrite
    {
        const int d = lane;
        const float bias = cb[n * HD + d];
        float wt[9];
        #pragma unroll
        for (int i = 0; i < 9; i++) wt[i] = cw[(n * HD + d) * 9 + i];
        const int r0 = wid * 4;                 // absolute image rows in window
        const __half* Vs = sm + VOFFH;

        float rows[3][8];
        #pragma unroll
        for (int cc = 0; cc < 8; cc++) {
            rows[0][cc] = (r0 == 0) ? 0.f
                        : __half2float(Vs[((r0 - 1) * 8 + cc) * 40 + d]);
            rows[1][cc] = __half2float(Vs[(r0 * 8 + cc) * 40 + d]);
        }
        #pragma unroll
        for (int rr = 0; rr < 4; rr++) {
            const int prv = rr % 3, cur3 = (rr + 1) % 3, nxt = (rr + 2) % 3;
            const int rn = r0 + rr + 1;
            #pragma unroll
            for (int cc = 0; cc < 8; cc++)
                rows[nxt][cc] = (rn >= RESO) ? 0.f
                              : __half2float(Vs[(rn * 8 + cc) * 40 + d]);
            #pragma unroll
            for (int cc = 0; cc < 8; cc++) {
                float acc = bias;
                if (cc > 0) {
                    acc += rows[prv][cc - 1] * wt[0];
                    acc += rows[cur3][cc - 1] * wt[3];
                    acc += rows[nxt][cc - 1] * wt[6];
                }
                acc += rows[prv][cc] * wt[1];
                acc += rows[cur3][cc] * wt[4];
                acc += rows[nxt][cc] * wt[7];
                if (cc < 7) {
                    acc += rows[prv][cc + 1] * wt[2];
                    acc += rows[cur3][cc + 1] * wt[5];
                    acc += rows[nxt][cc + 1] * wt[8];
                }
                int ltok = wid * 32 + rr * 8 + cc;
                sm[ltok * 40 + d] = __float2half_rn(acc);
            }
        }
    }
    __syncthreads();

    // ---- epilogue: O/lsum + lepe(smem) -> fp16 chunk-major padded g_xh ----
    #pragma unroll
    for (int mt = 0; mt < 2; mt++) {
        const float il = 1.f / lsl[mt];
        const float ih = 1.f / lsh[mt];
        const int lt0 = m0 + mt * 16 + g;                // local token
        const size_t grow = (size_t)w * WIN + lt0;
        #pragma unroll
        for (int ntd = 0; ntd < 4; ntd++) {
            int ch = ntd * 8 + t2;
            float2 e0 = __half22float2(*(const __half2*)(sm + lt0 * 40 + ch));
            float2 e1 = __half22float2(*(const __half2*)(sm + (lt0 + 8) * 40 + ch));
            size_t x0 = (size_t)n * PLANE + grow * 40 + ch;
            size_t x1 = x0 + 8 * 40;
            *(__half2*)(g_xh + x0) = __floats2half2_rn(O[mt][ntd][0] * il + e0.x,
                                                       O[mt][ntd][1] * il + e0.y);
            *(__half2*)(g_xh + x1) = __floats2half2_rn(O[mt][ntd][2] * ih + e1.x,
                                                       O[mt][ntd][3] * ih + e1.y);
        }
    }
}

// ---------------------------------------------------------------------------
// Projection: out = x @ W^T + b. CTA 128m x 64n, 8 warps (4m x 2n) 32x32 tiles.
// cp.async 3-stage pipeline, one sync/chunk, ldmatrix fragments, 3 CTAs/SM.
// ---------------------------------------------------------------------------
#define PROJ_SMEM_BYTES (3 * (128 * 40 + 64 * 40) * 2)   // 46080

__global__ __launch_bounds__(256, 3) void proj_hmma(const float* __restrict__ bias,
                                                    float* __restrict__ out) {
    extern __shared__ __half psm[];
    const int tid = threadIdx.x;
    const int m0 = blockIdx.y * 128, n0 = blockIdx.x * 64;
    const int wid = tid >> 5, lane = tid & 31;
    const int g = lane >> 2, t2 = (lane & 3) * 2;
    const int wm = (wid >> 1) * 32, wn = (wid & 1) * 32;
    const uint32_t sb = smem_u32(psm);

    auto fill = [&](int c) {
        int s = c % 3;
        uint32_t abase = sb + (uint32_t)s * 10240u;
        const __half* asrc = g_xh + (size_t)c * PLANE + (size_t)m0 * 40;
        #pragma unroll
        for (int i = 0; i < 3; i++) {
            int idx = tid + i * 256;
            if (idx < 640) CP_ASYNC16(abase + idx * 16, asrc + idx * 8);
        }
        uint32_t bbase = sb + 30720u + (uint32_t)s * 5120u;
        const __half* bsrc = g_wh + (size_t)c * (DIMC * 40) + (size_t)n0 * 40;
        #pragma unroll
        for (int i = 0; i < 2; i++) {
            int idx = tid + i * 256;
            if (idx < 320) CP_ASYNC16(bbase + idx * 16, bsrc + idx * 8);
        }
        CP_COMMIT();
    };

    float D[2][4][4];
    #pragma unroll
    for (int mt = 0; mt < 2; mt++)
        #pragma unroll
        for (int nt = 0; nt < 4; nt++)
            #pragma unroll
            for (int e = 0; e < 4; e++) D[mt][nt][e] = 0.f;

    fill(0); fill(1);

    const uint32_t aoff = (uint32_t)(wm * 80 + (lane & 15) * 80 + (lane >> 4) * 16);
    const uint32_t boff = (uint32_t)(30720 + (wn + (lane & 7)) * 80 + (lane >> 3) * 16);

    #pragma unroll
    for (int c = 0; c < 8; c++) {
        if (c < 7) asm volatile("cp.async.wait_group 1;");
        else       asm volatile("cp.async.wait_group 0;");
        __syncthreads();
        if (c + 2 < 8) fill(c + 2);

        const uint32_t aconst = sb + (uint32_t)(c % 3) * 10240u + aoff;
        const uint32_t bconst = sb + (uint32_t)(c % 3) * 5120u + boff;

        uint32_t a[2][2][4];
        #pragma unroll
        for (int mt = 0; mt < 2; mt++)
            #pragma unroll
            for (int ks = 0; ks < 2; ks++)
                LDSM_X4(a[mt][ks][0], a[mt][ks][1], a[mt][ks][2], a[mt][ks][3],
                        aconst + (uint32_t)(mt * 1280 + ks * 32));
        uint32_t bb[4][2][2];
        #pragma unroll
        for (int nt = 0; nt < 4; nt++)
            LDSM_X4(bb[nt][0][0], bb[nt][0][1], bb[nt][1][0], bb[nt][1][1],
                    bconst + (uint32_t)(nt * 640));
        #pragma unroll
        for (int mt = 0; mt < 2; mt++)
            #pragma unroll
            for (int nt = 0; nt < 4; nt++)
                #pragma unroll
                for (int ks = 0; ks < 2; ks++)
                    mma16816(D[mt][nt], a[mt][ks], bb[nt][ks]);
    }

    // ---- scatter epilogue with bias ----
    #pragma unroll
    for (int mt = 0; mt < 2; mt++) {
        #pragma unroll
        for (int nt = 0; nt < 4; nt++) {
            int col = n0 + wn + nt * 8 + t2;
            float2 bv = *(const float2*)&bias[col];
            #pragma unroll
            for (int half = 0; half < 2; half++) {
                int mrow = m0 + wm + mt * 16 + g + half * 8;
                int wI = mrow >> 9, t = mrow & 511;
                int bI = wI >> 3, jI = wI & 7;
                int rI = t >> 3, c2I = t & 7;
                size_t o = ((size_t)bI * LTOK + rI * RESO + jI * 8 + c2I) * DIMC + col;
                float2 r;
                r.x = D[mt][nt][half * 2 + 0] + bv.x;
                r.y = D[mt][nt][half * 2 + 1] + bv.y;
                *(float2*)&out[o] = r;
            }
        }
    }
}

// ---------------------------------------------------------------------------
extern "C" void kernel_launch(void* const* d_in, const int* in_sizes, int n_in,
                              void* d_out, int out_size) {
    (void)in_sizes; (void)n_in; (void)out_size;
    const float* qkv    = (const float*)d_in[0];
    const float* scale  = (const float*)d_in[1];
    const float* proj_w = (const float*)d_in[2];
    const float* proj_b = (const float*)d_in[3];
    const float* conv_w = (const float*)d_in[4];
    const float* conv_b = (const float*)d_in[5];
    float* out = (float*)d_out;

    cudaFuncSetAttribute(attn_hmma, cudaFuncAttributeMaxDynamicSharedMemorySize,
                         ATTN_SMEM_BYTES);
    attn_hmma<<<dim3(NWTOT, NH), 512, ATTN_SMEM_BYTES>>>(qkv, scale, conv_w, conv_b,
                                                         proj_w);

    cudaFuncSetAttribute(proj_hmma, cudaFuncAttributeMaxDynamicSharedMemorySize,
                         PROJ_SMEM_BYTES);
    proj_hmma<<<dim3(DIMC / 64, MROWS / 128), 256, PROJ_SMEM_BYTES>>>(proj_b, out);
}

// round 15
// speedup vs baseline: 1.1863x; 1.1863x over previous
#include <cuda_runtime.h>
#include <cuda_fp16.h>
#include <cstdint>

#define BATCH 8
#define RESO 64
#define DIMC 256
#define NH 8
#define HD 32
#define WIN 512
#define NWTOT 64
#define LTOK 4096
#define MROWS (NWTOT * WIN)          // 32768
#define PLANE ((size_t)MROWS * 40)   // halves per chunk-plane of g_xh

// ---------------------------------------------------------------------------
// Scratch (__device__ globals: allocation-free rule)
// ---------------------------------------------------------------------------
__device__ __align__(16) __half g_xh[(size_t)NH * PLANE];    // [chunk(=head)][row][40]
__device__ __align__(16) __half g_wh[(size_t)8 * DIMC * 40]; // [chunk][col][40]

// ---------------------------------------------------------------------------
// Helpers
// ---------------------------------------------------------------------------
__device__ __forceinline__ uint32_t packh2(float x, float y) {
    __half2 h = __floats2half2_rn(x, y);
    return *reinterpret_cast<uint32_t*>(&h);
}
__device__ __forceinline__ uint32_t smem_u32(const void* p) {
    uint32_t a;
    asm("{ .reg .u64 t; cvta.to.shared.u64 t, %1; cvt.u32.u64 %0, t; }"
        : "=r"(a) : "l"(p));
    return a;
}
__device__ __forceinline__ void mma16816(float d[4], const uint32_t a[4],
                                         const uint32_t b[2]) {
    asm volatile(
        "mma.sync.aligned.m16n8k16.row.col.f32.f16.f16.f32 "
        "{%0,%1,%2,%3}, {%4,%5,%6,%7}, {%8,%9}, {%0,%1,%2,%3};\n"
        : "+f"(d[0]), "+f"(d[1]), "+f"(d[2]), "+f"(d[3])
        : "r"(a[0]), "r"(a[1]), "r"(a[2]), "r"(a[3]), "r"(b[0]), "r"(b[1]));
}
__device__ __forceinline__ void mma16816_f16(uint32_t d[2], const uint32_t a[4],
                                             const uint32_t b[2]) {
    asm volatile(
        "mma.sync.aligned.m16n8k16.row.col.f16.f16.f16.f16 "
        "{%0,%1}, {%2,%3,%4,%5}, {%6,%7}, {%0,%1};\n"
        : "+r"(d[0]), "+r"(d[1])
        : "r"(a[0]), "r"(a[1]), "r"(a[2]), "r"(a[3]), "r"(b[0]), "r"(b[1]));
}
#define LDSM_X4(r0, r1, r2, r3, addr) \
    asm volatile("ldmatrix.sync.aligned.m8n8.x4.shared.b16 {%0,%1,%2,%3}, [%4];" \
                 : "=r"(r0), "=r"(r1), "=r"(r2), "=r"(r3) : "r"(addr))
#define LDSM_X4_T(r0, r1, r2, r3, addr) \
    asm volatile("ldmatrix.sync.aligned.m8n8.x4.trans.shared.b16 {%0,%1,%2,%3}, [%4];" \
                 : "=r"(r0), "=r"(r1), "=r"(r2), "=r"(r3) : "r"(addr))
#define EX2F16X2(d, s) \
    asm("ex2.approx.f16x2 %0, %1;" : "=r"(d) : "r"(s))
#define CP_ASYNC16(dst, src) \
    asm volatile("cp.async.cg.shared.global [%0], [%1], 16;" :: "r"(dst), "l"(src))
#define CP_COMMIT() asm volatile("cp.async.commit_group;")

// ---------------------------------------------------------------------------
// HMMA flash attention + fused LePE (+ fused W-preconvert in first-wave CTAs).
// CTA = (window, head, half): grid (64, 8, 2), 256 threads, 2 CTAs/SM.
// K and V both [key][40] fp16 in smem (converted in the fill); V fragments via
// ldmatrix.trans. After the MMA loop the dead K region holds the LePE output.
// smem: K [512][40] + V [512][40] = 80 KB.
// ---------------------------------------------------------------------------
#define VOFFH (512 * 40)           // halves
#define VOFFB (512 * 40 * 2)       // bytes (40960)
#define ATTN_SMEM_BYTES (2 * 512 * 40 * 2)   // 81920

__global__ __launch_bounds__(256, 2) void attn_hmma(const float* __restrict__ qkv,
                                                    const float* __restrict__ scale_p,
                                                    const float* __restrict__ cw,
                                                    const float* __restrict__ cb,
                                                    const float* __restrict__ W) {
    extern __shared__ __half sm[];
    const int tid = threadIdx.x;
    const int w = blockIdx.x, n = blockIdx.y, z = blockIdx.z;
    const int b = w >> 3, j = w & 7;
    const float qscale = scale_p[0] * 1.44269504f;
    const float* kp = qkv + (size_t)BATCH * LTOK * DIMC;
    const float* vp = kp + (size_t)BATCH * LTOK * DIMC;

    // ---- fused prep_w: 64 first-wave CTAs convert W (8192 vec8 items) ----
    if (n == 0 && z == 0 && tid < 128) {
        const int gid = w * 128 + tid;              // 0..8191
        const int c = gid >> 5, k0 = (gid & 31) * 8;
        float4 w0 = *(const float4*)&W[(size_t)c * DIMC + k0];
        float4 w1 = *(const float4*)&W[(size_t)c * DIMC + k0 + 4];
        union { uint4 u; __half2 h[4]; } pk;
        pk.h[0] = __floats2half2_rn(w0.x, w0.y);
        pk.h[1] = __floats2half2_rn(w0.z, w0.w);
        pk.h[2] = __floats2half2_rn(w1.x, w1.y);
        pk.h[3] = __floats2half2_rn(w1.z, w1.w);
        *(uint4*)(g_wh + (size_t)(k0 >> 5) * (DIMC * 40) + c * 40 + (k0 & 31)) = pk.u;
    }

    // ---- fill K & V (convert fp32->fp16), layout [key][40] ----
    #pragma unroll
    for (int it = 0; it < 16; it++) {
        int i = tid + it * 256;
        int s = i >> 3, f4 = i & 7;
        int rs = s >> 3, cs = s & 7;
        size_t gbase = ((size_t)b * LTOK + rs * RESO + j * 8 + cs) * DIMC + n * HD + f4 * 4;
        float4 kf = *(const float4*)(kp + gbase);
        float4 vf = *(const float4*)(vp + gbase);
        uint2 hk, hv;
        hk.x = packh2(kf.x, kf.y); hk.y = packh2(kf.z, kf.w);
        hv.x = packh2(vf.x, vf.y); hv.y = packh2(vf.z, vf.w);
        *(uint2*)(sm + s * 40 + f4 * 4)         = hk;
        *(uint2*)(sm + VOFFH + s * 40 + f4 * 4) = hv;
    }

    const int wid = tid >> 5, lane = tid & 31;
    const int g = lane >> 2, t2 = (lane & 3) * 2;
    const int m0 = z * 256 + wid * 32;
    const bool mzero = (j == 7) && ((g < 4) != ((lane & 3) < 2));

    // ---- persistent Q fragments (2 m-tiles, fp16, scaled) ----
    uint32_t qh[2][2][4];
    #pragma unroll
    for (int mt = 0; mt < 2; mt++) {
        #pragma unroll
        for (int rh = 0; rh < 2; rh++) {
            int row = m0 + mt * 16 + g + rh * 8;
            int rs = row >> 3, cs = row & 7;
            const float* src = qkv + ((size_t)b * LTOK + rs * RESO + j * 8 + cs) * DIMC + n * HD;
            #pragma unroll
            for (int ks = 0; ks < 2; ks++) {
                #pragma unroll
                for (int ch = 0; ch < 2; ch++) {
                    float2 f = *(const float2*)(src + ks * 16 + ch * 8 + t2);
                    qh[mt][ks][rh + ch * 2] = packh2(f.x * qscale, f.y * qscale);
                }
            }
        }
    }
    __syncthreads();

    const uint32_t sb = smem_u32(sm);
    const uint32_t kconst = sb + (uint32_t)((lane & 7) * 80 + (lane >> 3) * 16);
    const uint32_t vconst = sb + VOFFB + (uint32_t)((lane & 15) * 80 + (lane >> 4) * 16);

    float O[2][4][4];
    float lsl[2] = {0.f, 0.f}, lsh[2] = {0.f, 0.f};
    #pragma unroll
    for (int mt = 0; mt < 2; mt++)
        #pragma unroll
        for (int nt = 0; nt < 4; nt++)
            #pragma unroll
            for (int e = 0; e < 4; e++) O[mt][nt][e] = 0.f;

    // fp16x2 QK accumulators; after in-place ex2 these ARE the PV A-fragments.
    uint32_t S16[2][2][2][2];
    uint32_t kb[2][2][2];

    // ---- prologue: kb(0), QK(0) -> S16[0] ----
    LDSM_X4(kb[0][0][0], kb[0][0][1], kb[0][1][0], kb[0][1][1], kconst);
    LDSM_X4(kb[1][0][0], kb[1][0][1], kb[1][1][0], kb[1][1][1], kconst + 640u);
    #pragma unroll
    for (int mt = 0; mt < 2; mt++)
        #pragma unroll
        for (int nt = 0; nt < 2; nt++) {
            S16[0][mt][nt][0] = 0u; S16[0][mt][nt][1] = 0u;
            #pragma unroll
            for (int ks = 0; ks < 2; ks++)
                mma16816_f16(S16[0][mt][nt], qh[mt][ks], kb[nt][ks]);
        }

    #pragma unroll 2
    for (int step = 0; step < 32; step++) {
        const int cur = step & 1, nb = cur ^ 1;
        if (step < 31) {
            LDSM_X4(kb[0][0][0], kb[0][0][1], kb[0][1][0], kb[0][1][1],
                    kconst + (uint32_t)(step + 1) * 1280u);
            LDSM_X4(kb[1][0][0], kb[1][0][1], kb[1][1][0], kb[1][1][1],
                    kconst + (uint32_t)(step + 1) * 1280u + 640u);
        }
        // V fragments for step via ldmatrix.trans (V is [key][40])
        uint32_t vb[4][2];
        LDSM_X4_T(vb[0][0], vb[0][1], vb[1][0], vb[1][1],
                  vconst + (uint32_t)step * 1280u);
        LDSM_X4_T(vb[2][0], vb[2][1], vb[3][0], vb[3][1],
                  vconst + (uint32_t)step * 1280u + 32u);

        // ---- softmax: in-place ex2 on fp16 S; lsum via HADD2 + fp32 ----
        #pragma unroll
        for (int mt = 0; mt < 2; mt++) {
            #pragma unroll
            for (int nt = 0; nt < 2; nt++) {
                uint32_t p0, p1;
                EX2F16X2(p0, S16[cur][mt][nt][0]);
                EX2F16X2(p1, S16[cur][mt][nt][1]);
                S16[cur][mt][nt][0] = mzero ? 0u : p0;
                S16[cur][mt][nt][1] = mzero ? 0u : p1;
            }
            __half2 tl = __hadd2(*(__half2*)&S16[cur][mt][0][0],
                                 *(__half2*)&S16[cur][mt][1][0]);
            __half2 th = __hadd2(*(__half2*)&S16[cur][mt][0][1],
                                 *(__half2*)&S16[cur][mt][1][1]);
            float2 fl = __half22float2(tl);
            float2 fh = __half22float2(th);
            lsl[mt] += fl.x + fl.y;
            lsh[mt] += fh.x + fh.y;
        }

        // ---- QK(step+1) overlaps the ex2->PV chain ----
        if (step < 31) {
            #pragma unroll
            for (int mt = 0; mt < 2; mt++)
                #pragma unroll
                for (int nt = 0; nt < 2; nt++) {
                    S16[nb][mt][nt][0] = 0u; S16[nb][mt][nt][1] = 0u;
                    #pragma unroll
                    for (int ks = 0; ks < 2; ks++)
                        mma16816_f16(S16[nb][mt][nt], qh[mt][ks], kb[nt][ks]);
                }
        }

        // ---- PV(step) ----
        #pragma unroll
        for (int mt = 0; mt < 2; mt++)
            #pragma unroll
            for (int ntd = 0; ntd < 4; ntd++)
                mma16816(O[mt][ntd], &S16[cur][mt][0][0], vb[ntd]);
    }

    // ---- quad reduction of row sums ----
    #pragma unroll
    for (int mt = 0; mt < 2; mt++) {
        lsl[mt] += __shfl_xor_sync(0xffffffffu, lsl[mt], 1);
        lsl[mt] += __shfl_xor_sync(0xffffffffu, lsl[mt], 2);
        lsh[mt] += __shfl_xor_sync(0xffffffffu, lsh[mt], 1);
        lsh[mt] += __shfl_xor_sync(0xffffffffu, lsh[mt], 2);
    }

    // ---- fused LePE conv: K region is dead; write lepe [256 tok][40] there.
    // Warp wid covers local tokens wid*32..wid*32+31 (4 image rows); lane = d.
    __syncthreads();     // all K reads done before overwrite
    {
        const int d = lane;
        const float bias = cb[n * HD + d];
        float wt[9];
        #pragma unroll
        for (int i = 0; i < 9; i++) wt[i] = cw[(n * HD + d) * 9 + i];
        const int r0 = z * 32 + wid * 4;        // absolute image rows in window
        const __half* Vs = sm + VOFFH;

        float rows[3][8];
        #pragma unroll
        for (int cc = 0; cc < 8; cc++) {
            rows[0][cc] = (r0 == 0) ? 0.f
                        : __half2float(Vs[((r0 - 1) * 8 + cc) * 40 + d]);
            rows[1][cc] = __half2float(Vs[(r0 * 8 + cc) * 40 + d]);
        }
        #pragma unroll
        for (int rr = 0; rr < 4; rr++) {
            const int prv = rr % 3, cur3 = (rr + 1) % 3, nxt = (rr + 2) % 3;
            const int rn = r0 + rr + 1;
            #pragma unroll
            for (int cc = 0; cc < 8; cc++)
                rows[nxt][cc] = (rn >= RESO) ? 0.f
                              : __half2float(Vs[(rn * 8 + cc) * 40 + d]);
            #pragma unroll
            for (int cc = 0; cc < 8; cc++) {
                float acc = bias;
                if (cc > 0) {
                    acc += rows[prv][cc - 1] * wt[0];
                    acc += rows[cur3][cc - 1] * wt[3];
                    acc += rows[nxt][cc - 1] * wt[6];
                }
                acc += rows[prv][cc] * wt[1];
                acc += rows[cur3][cc] * wt[4];
                acc += rows[nxt][cc] * wt[7];
                if (cc < 7) {
                    acc += rows[prv][cc + 1] * wt[2];
                    acc += rows[cur3][cc + 1] * wt[5];
                    acc += rows[nxt][cc + 1] * wt[8];
                }
                int ltok = wid * 32 + rr * 8 + cc;
                sm[ltok * 40 + d] = __float2half_rn(acc);
            }
        }
    }
    __syncthreads();

    // ---- epilogue: O/lsum + lepe(smem) -> fp16 chunk-major padded g_xh ----
    #pragma unroll
    for (int mt = 0; mt < 2; mt++) {
        const float il = 1.f / lsl[mt];
        const float ih = 1.f / lsh[mt];
        const int lt0 = wid * 32 + mt * 16 + g;          // local token
        const size_t grow = (size_t)w * WIN + z * 256 + lt0;
        #pragma unroll
        for (int ntd = 0; ntd < 4; ntd++) {
            int ch = ntd * 8 + t2;
            float2 e0 = __half22float2(*(const __half2*)(sm + lt0 * 40 + ch));
            float2 e1 = __half22float2(*(const __half2*)(sm + (lt0 + 8) * 40 + ch));
            size_t x0 = (size_t)n * PLANE + grow * 40 + ch;
            size_t x1 = x0 + 8 * 40;
            *(__half2*)(g_xh + x0) = __floats2half2_rn(O[mt][ntd][0] * il + e0.x,
                                                       O[mt][ntd][1] * il + e0.y);
            *(__half2*)(g_xh + x1) = __floats2half2_rn(O[mt][ntd][2] * ih + e1.x,
                                                       O[mt][ntd][3] * ih + e1.y);
        }
    }
}

// ---------------------------------------------------------------------------
// Projection: out = x @ W^T + b. CTA 128m x 64n, 8 warps (4m x 2n) 32x32 tiles.
// cp.async 3-stage pipeline, one sync/chunk, ldmatrix fragments, 3 CTAs/SM.
// ---------------------------------------------------------------------------
#define PROJ_SMEM_BYTES (3 * (128 * 40 + 64 * 40) * 2)   // 46080

__global__ __launch_bounds__(256, 3) void proj_hmma(const float* __restrict__ bias,
                                                    float* __restrict__ out) {
    extern __shared__ __half psm[];
    const int tid = threadIdx.x;
    const int m0 = blockIdx.y * 128, n0 = blockIdx.x * 64;
    const int wid = tid >> 5, lane = tid & 31;
    const int g = lane >> 2, t2 = (lane & 3) * 2;
    const int wm = (wid >> 1) * 32, wn = (wid & 1) * 32;
    const uint32_t sb = smem_u32(psm);

    auto fill = [&](int c) {
        int s = c % 3;
        uint32_t abase = sb + (uint32_t)s * 10240u;
        const __half* asrc = g_xh + (size_t)c * PLANE + (size_t)m0 * 40;
        #pragma unroll
        for (int i = 0; i < 3; i++) {
            int idx = tid + i * 256;
            if (idx < 640) CP_ASYNC16(abase + idx * 16, asrc + idx * 8);
        }
        uint32_t bbase = sb + 30720u + (uint32_t)s * 5120u;
        const __half* bsrc = g_wh + (size_t)c * (DIMC * 40) + (size_t)n0 * 40;
        #pragma unroll
        for (int i = 0; i < 2; i++) {
            int idx = tid + i * 256;
            if (idx < 320) CP_ASYNC16(bbase + idx * 16, bsrc + idx * 8);
        }
        CP_COMMIT();
    };

    float D[2][4][4];
    #pragma unroll
    for (int mt = 0; mt < 2; mt++)
        #pragma unroll
        for (int nt = 0; nt < 4; nt++)
            #pragma unroll
            for (int e = 0; e < 4; e++) D[mt][nt][e] = 0.f;

    fill(0); fill(1);

    const uint32_t aoff = (uint32_t)(wm * 80 + (lane & 15) * 80 + (lane >> 4) * 16);
    const uint32_t boff = (uint32_t)(30720 + (wn + (lane & 7)) * 80 + (lane >> 3) * 16);

    #pragma unroll
    for (int c = 0; c < 8; c++) {
        if (c < 7) asm volatile("cp.async.wait_group 1;");
        else       asm volatile("cp.async.wait_group 0;");
        __syncthreads();
        if (c + 2 < 8) fill(c + 2);

        const uint32_t aconst = sb + (uint32_t)(c % 3) * 10240u + aoff;
        const uint32_t bconst = sb + (uint32_t)(c % 3) * 5120u + boff;

        uint32_t a[2][2][4];
        #pragma unroll
        for (int mt = 0; mt < 2; mt++)
            #pragma unroll
            for (int ks = 0; ks < 2; ks++)
                LDSM_X4(a[mt][ks][0], a[mt][ks][1], a[mt][ks][2], a[mt][ks][3],
                        aconst + (uint32_t)(mt * 1280 + ks * 32));
        uint32_t bb[4][2][2];
        #pragma unroll
        for (int nt = 0; nt < 4; nt++)
            LDSM_X4(bb[nt][0][0], bb[nt][0][1], bb[nt][1][0], bb[nt][1][1],
                    bconst + (uint32_t)(nt * 640));
        #pragma unroll
        for (int mt = 0; mt < 2; mt++)
            #pragma unroll
            for (int nt = 0; nt < 4; nt++)
                #pragma unroll
                for (int ks = 0; ks < 2; ks++)
                    mma16816(D[mt][nt], a[mt][ks], bb[nt][ks]);
    }

    // ---- scatter epilogue with bias ----
    #pragma unroll
    for (int mt = 0; mt < 2; mt++) {
        #pragma unroll
        for (int nt = 0; nt < 4; nt++) {
            int col = n0 + wn + nt * 8 + t2;
            float2 bv = *(const float2*)&bias[col];
            #pragma unroll
            for (int half = 0; half < 2; half++) {
                int mrow = m0 + wm + mt * 16 + g + half * 8;
                int wI = mrow >> 9, t = mrow & 511;
                int bI = wI >> 3, jI = wI & 7;
                int rI = t >> 3, c2I = t & 7;
                size_t o = ((size_t)bI * LTOK + rI * RESO + jI * 8 + c2I) * DIMC + col;
                float2 r;
                r.x = D[mt][nt][half * 2 + 0] + bv.x;
                r.y = D[mt][nt][half * 2 + 1] + bv.y;
                *(float2*)&out[o] = r;
            }
        }
    }
}

// ---------------------------------------------------------------------------
extern "C" void kernel_launch(void* const* d_in, const int* in_sizes, int n_in,
                              void* d_out, int out_size) {
    (void)in_sizes; (void)n_in; (void)out_size;
    const float* qkv    = (const float*)d_in[0];
    const float* scale  = (const float*)d_in[1];
    const float* proj_w = (const float*)d_in[2];
    const float* proj_b = (const float*)d_in[3];
    const float* conv_w = (const float*)d_in[4];
    const float* conv_b = (const float*)d_in[5];
    float* out = (float*)d_out;

    cudaFuncSetAttribute(attn_hmma, cudaFuncAttributeMaxDynamicSharedMemorySize,
                         ATTN_SMEM_BYTES);
    attn_hmma<<<dim3(NWTOT, NH, 2), 256, ATTN_SMEM_BYTES>>>(qkv, scale, conv_w, conv_b,
                                                            proj_w);

    cudaFuncSetAttribute(proj_hmma, cudaFuncAttributeMaxDynamicSharedMemorySize,
                         PROJ_SMEM_BYTES);
    proj_hmma<<<dim3(DIMC / 64, MROWS / 128), 256, PROJ_SMEM_BYTES>>>(proj_b, out);
}

// round 16
// speedup vs baseline: 1.2239x; 1.0317x over previous
#include <cuda_runtime.h>
#include <cuda_fp16.h>
#include <cstdint>

#define BATCH 8
#define RESO 64
#define DIMC 256
#define NH 8
#define HD 32
#define WIN 512
#define NWTOT 64
#define LTOK 4096
#define MROWS (NWTOT * WIN)          // 32768
#define PLANE ((size_t)MROWS * 40)   // halves per chunk-plane of g_xh

// ---------------------------------------------------------------------------
// Scratch (__device__ globals: allocation-free rule)
// ---------------------------------------------------------------------------
__device__ __align__(16) __half g_xh[(size_t)NH * PLANE];    // [chunk(=head)][row][40]
__device__ __align__(16) __half g_wh[(size_t)8 * DIMC * 40]; // [chunk][col][40]

// ---------------------------------------------------------------------------
// Helpers
// ---------------------------------------------------------------------------
__device__ __forceinline__ uint32_t packh2(float x, float y) {
    __half2 h = __floats2half2_rn(x, y);
    return *reinterpret_cast<uint32_t*>(&h);
}
__device__ __forceinline__ uint32_t smem_u32(const void* p) {
    uint32_t a;
    asm("{ .reg .u64 t; cvta.to.shared.u64 t, %1; cvt.u32.u64 %0, t; }"
        : "=r"(a) : "l"(p));
    return a;
}
__device__ __forceinline__ void mma16816(float d[4], const uint32_t a[4],
                                         const uint32_t b[2]) {
    asm volatile(
        "mma.sync.aligned.m16n8k16.row.col.f32.f16.f16.f32 "
        "{%0,%1,%2,%3}, {%4,%5,%6,%7}, {%8,%9}, {%0,%1,%2,%3};\n"
        : "+f"(d[0]), "+f"(d[1]), "+f"(d[2]), "+f"(d[3])
        : "r"(a[0]), "r"(a[1]), "r"(a[2]), "r"(a[3]), "r"(b[0]), "r"(b[1]));
}
__device__ __forceinline__ void mma16816_f16(uint32_t d[2], const uint32_t a[4],
                                             const uint32_t b[2]) {
    asm volatile(
        "mma.sync.aligned.m16n8k16.row.col.f16.f16.f16.f16 "
        "{%0,%1}, {%2,%3,%4,%5}, {%6,%7}, {%0,%1};\n"
        : "+r"(d[0]), "+r"(d[1])
        : "r"(a[0]), "r"(a[1]), "r"(a[2]), "r"(a[3]), "r"(b[0]), "r"(b[1]));
}
#define LDSM_X4(r0, r1, r2, r3, addr) \
    asm volatile("ldmatrix.sync.aligned.m8n8.x4.shared.b16 {%0,%1,%2,%3}, [%4];" \
                 : "=r"(r0), "=r"(r1), "=r"(r2), "=r"(r3) : "r"(addr))
#define LDSM_X4_T(r0, r1, r2, r3, addr) \
    asm volatile("ldmatrix.sync.aligned.m8n8.x4.trans.shared.b16 {%0,%1,%2,%3}, [%4];" \
                 : "=r"(r0), "=r"(r1), "=r"(r2), "=r"(r3) : "r"(addr))
#define EX2F16X2(d, s) \
    asm("ex2.approx.f16x2 %0, %1;" : "=r"(d) : "r"(s))
#define CP_ASYNC16(dst, src) \
    asm volatile("cp.async.cg.shared.global [%0], [%1], 16;" :: "r"(dst), "l"(src))
#define CP_COMMIT() asm volatile("cp.async.commit_group;")

// ---------------------------------------------------------------------------
// HMMA flash attention + fused LePE (+ fused W-preconvert in first-wave CTAs).
// CTA = (half, window, head): grid (2, 64, 8) -- z fastest so the two CTAs of
// one (window, head) are launch-adjacent and the second K/V fill hits L2.
// 256 threads, 2 CTAs/SM. smem: K [512][40] + V [512][40] = 80 KB.
// ---------------------------------------------------------------------------
#define VOFFH (512 * 40)           // halves
#define VOFFB (512 * 40 * 2)       // bytes (40960)
#define ATTN_SMEM_BYTES (2 * 512 * 40 * 2)   // 81920

__global__ __launch_bounds__(256, 2) void attn_hmma(const float* __restrict__ qkv,
                                                    const float* __restrict__ scale_p,
                                                    const float* __restrict__ cw,
                                                    const float* __restrict__ cb,
                                                    const float* __restrict__ W) {
    extern __shared__ __half sm[];
    const int tid = threadIdx.x;
    const int z = blockIdx.x, w = blockIdx.y, n = blockIdx.z;
    const int b = w >> 3, j = w & 7;
    const float qscale = scale_p[0] * 1.44269504f;
    const float* kp = qkv + (size_t)BATCH * LTOK * DIMC;
    const float* vp = kp + (size_t)BATCH * LTOK * DIMC;

    // ---- fused prep_w: 64 first-wave CTAs convert W (8192 vec8 items) ----
    if (n == 0 && z == 0 && tid < 128) {
        const int gid = w * 128 + tid;              // 0..8191
        const int c = gid >> 5, k0 = (gid & 31) * 8;
        float4 w0 = *(const float4*)&W[(size_t)c * DIMC + k0];
        float4 w1 = *(const float4*)&W[(size_t)c * DIMC + k0 + 4];
        union { uint4 u; __half2 h[4]; } pk;
        pk.h[0] = __floats2half2_rn(w0.x, w0.y);
        pk.h[1] = __floats2half2_rn(w0.z, w0.w);
        pk.h[2] = __floats2half2_rn(w1.x, w1.y);
        pk.h[3] = __floats2half2_rn(w1.z, w1.w);
        *(uint4*)(g_wh + (size_t)(k0 >> 5) * (DIMC * 40) + c * 40 + (k0 & 31)) = pk.u;
    }

    // ---- fill K & V (convert fp32->fp16), layout [key][40] ----
    #pragma unroll
    for (int it = 0; it < 16; it++) {
        int i = tid + it * 256;
        int s = i >> 3, f4 = i & 7;
        int rs = s >> 3, cs = s & 7;
        size_t gbase = ((size_t)b * LTOK + rs * RESO + j * 8 + cs) * DIMC + n * HD + f4 * 4;
        float4 kf = *(const float4*)(kp + gbase);
        float4 vf = *(const float4*)(vp + gbase);
        uint2 hk, hv;
        hk.x = packh2(kf.x, kf.y); hk.y = packh2(kf.z, kf.w);
        hv.x = packh2(vf.x, vf.y); hv.y = packh2(vf.z, vf.w);
        *(uint2*)(sm + s * 40 + f4 * 4)         = hk;
        *(uint2*)(sm + VOFFH + s * 40 + f4 * 4) = hv;
    }

    const int wid = tid >> 5, lane = tid & 31;
    const int g = lane >> 2, t2 = (lane & 3) * 2;
    const int m0 = z * 256 + wid * 32;
    const bool mzero = (j == 7) && ((g < 4) != ((lane & 3) < 2));

    // ---- persistent Q fragments (2 m-tiles, fp16, scaled) ----
    uint32_t qh[2][2][4];
    #pragma unroll
    for (int mt = 0; mt < 2; mt++) {
        #pragma unroll
        for (int rh = 0; rh < 2; rh++) {
            int row = m0 + mt * 16 + g + rh * 8;
            int rs = row >> 3, cs = row & 7;
            const float* src = qkv + ((size_t)b * LTOK + rs * RESO + j * 8 + cs) * DIMC + n * HD;
            #pragma unroll
            for (int ks = 0; ks < 2; ks++) {
                #pragma unroll
                for (int ch = 0; ch < 2; ch++) {
                    float2 f = *(const float2*)(src + ks * 16 + ch * 8 + t2);
                    qh[mt][ks][rh + ch * 2] = packh2(f.x * qscale, f.y * qscale);
                }
            }
        }
    }
    __syncthreads();

    const uint32_t sb = smem_u32(sm);
    const uint32_t kconst = sb + (uint32_t)((lane & 7) * 80 + (lane >> 3) * 16);
    const uint32_t vconst = sb + VOFFB + (uint32_t)((lane & 15) * 80 + (lane >> 4) * 16);

    float O[2][4][4];
    float lsl[2] = {0.f, 0.f}, lsh[2] = {0.f, 0.f};
    #pragma unroll
    for (int mt = 0; mt < 2; mt++)
        #pragma unroll
        for (int nt = 0; nt < 4; nt++)
            #pragma unroll
            for (int e = 0; e < 4; e++) O[mt][nt][e] = 0.f;

    // fp16x2 QK accumulators; after in-place ex2 these ARE the PV A-fragments.
    uint32_t S16[2][2][2][2];
    uint32_t kb[2][2][2];

    // ---- prologue: kb(0), QK(0) -> S16[0] ----
    LDSM_X4(kb[0][0][0], kb[0][0][1], kb[0][1][0], kb[0][1][1], kconst);
    LDSM_X4(kb[1][0][0], kb[1][0][1], kb[1][1][0], kb[1][1][1], kconst + 640u);
    #pragma unroll
    for (int mt = 0; mt < 2; mt++)
        #pragma unroll
        for (int nt = 0; nt < 2; nt++) {
            S16[0][mt][nt][0] = 0u; S16[0][mt][nt][1] = 0u;
            #pragma unroll
            for (int ks = 0; ks < 2; ks++)
                mma16816_f16(S16[0][mt][nt], qh[mt][ks], kb[nt][ks]);
        }

    #pragma unroll 2
    for (int step = 0; step < 32; step++) {
        const int cur = step & 1, nb = cur ^ 1;
        if (step < 31) {
            LDSM_X4(kb[0][0][0], kb[0][0][1], kb[0][1][0], kb[0][1][1],
                    kconst + (uint32_t)(step + 1) * 1280u);
            LDSM_X4(kb[1][0][0], kb[1][0][1], kb[1][1][0], kb[1][1][1],
                    kconst + (uint32_t)(step + 1) * 1280u + 640u);
        }
        // V fragments for step via ldmatrix.trans (V is [key][40])
        uint32_t vb[4][2];
        LDSM_X4_T(vb[0][0], vb[0][1], vb[1][0], vb[1][1],
                  vconst + (uint32_t)step * 1280u);
        LDSM_X4_T(vb[2][0], vb[2][1], vb[3][0], vb[3][1],
                  vconst + (uint32_t)step * 1280u + 32u);

        // ---- softmax: in-place ex2 on fp16 S; lsum via HADD2 + fp32 ----
        #pragma unroll
        for (int mt = 0; mt < 2; mt++) {
            #pragma unroll
            for (int nt = 0; nt < 2; nt++) {
                uint32_t p0, p1;
                EX2F16X2(p0, S16[cur][mt][nt][0]);
                EX2F16X2(p1, S16[cur][mt][nt][1]);
                S16[cur][mt][nt][0] = mzero ? 0u : p0;
                S16[cur][mt][nt][1] = mzero ? 0u : p1;
            }
            __half2 tl = __hadd2(*(__half2*)&S16[cur][mt][0][0],
                                 *(__half2*)&S16[cur][mt][1][0]);
            __half2 th = __hadd2(*(__half2*)&S16[cur][mt][0][1],
                                 *(__half2*)&S16[cur][mt][1][1]);
            float2 fl = __half22float2(tl);
            float2 fh = __half22float2(th);
            lsl[mt] += fl.x + fl.y;
            lsh[mt] += fh.x + fh.y;
        }

        // ---- QK(step+1) overlaps the ex2->PV chain ----
        if (step < 31) {
            #pragma unroll
            for (int mt = 0; mt < 2; mt++)
                #pragma unroll
                for (int nt = 0; nt < 2; nt++) {
                    S16[nb][mt][nt][0] = 0u; S16[nb][mt][nt][1] = 0u;
                    #pragma unroll
                    for (int ks = 0; ks < 2; ks++)
                        mma16816_f16(S16[nb][mt][nt], qh[mt][ks], kb[nt][ks]);
                }
        }

        // ---- PV(step) ----
        #pragma unroll
        for (int mt = 0; mt < 2; mt++)
            #pragma unroll
            for (int ntd = 0; ntd < 4; ntd++)
                mma16816(O[mt][ntd], &S16[cur][mt][0][0], vb[ntd]);
    }

    // ---- quad reduction of row sums ----
    #pragma unroll
    for (int mt = 0; mt < 2; mt++) {
        lsl[mt] += __shfl_xor_sync(0xffffffffu, lsl[mt], 1);
        lsl[mt] += __shfl_xor_sync(0xffffffffu, lsl[mt], 2);
        lsh[mt] += __shfl_xor_sync(0xffffffffu, lsh[mt], 1);
        lsh[mt] += __shfl_xor_sync(0xffffffffu, lsh[mt], 2);
    }

    // ---- fused LePE conv: K region is dead; write lepe [256 tok][40] there.
    __syncthreads();     // all K reads done before overwrite
    {
        const int d = lane;
        const float bias = cb[n * HD + d];
        float wt[9];
        #pragma unroll
        for (int i = 0; i < 9; i++) wt[i] = cw[(n * HD + d) * 9 + i];
        const int r0 = z * 32 + wid * 4;        // absolute image rows in window
        const __half* Vs = sm + VOFFH;

        float rows[3][8];
        #pragma unroll
        for (int cc = 0; cc < 8; cc++) {
            rows[0][cc] = (r0 == 0) ? 0.f
                        : __half2float(Vs[((r0 - 1) * 8 + cc) * 40 + d]);
            rows[1][cc] = __half2float(Vs[(r0 * 8 + cc) * 40 + d]);
        }
        #pragma unroll
        for (int rr = 0; rr < 4; rr++) {
            const int prv = rr % 3, cur3 = (rr + 1) % 3, nxt = (rr + 2) % 3;
            const int rn = r0 + rr + 1;
            #pragma unroll
            for (int cc = 0; cc < 8; cc++)
                rows[nxt][cc] = (rn >= RESO) ? 0.f
                              : __half2float(Vs[(rn * 8 + cc) * 40 + d]);
            #pragma unroll
            for (int cc = 0; cc < 8; cc++) {
                float acc = bias;
                if (cc > 0) {
                    acc += rows[prv][cc - 1] * wt[0];
                    acc += rows[cur3][cc - 1] * wt[3];
                    acc += rows[nxt][cc - 1] * wt[6];
                }
                acc += rows[prv][cc] * wt[1];
                acc += rows[cur3][cc] * wt[4];
                acc += rows[nxt][cc] * wt[7];
                if (cc < 7) {
                    acc += rows[prv][cc + 1] * wt[2];
                    acc += rows[cur3][cc + 1] * wt[5];
                    acc += rows[nxt][cc + 1] * wt[8];
                }
                int ltok = wid * 32 + rr * 8 + cc;
                sm[ltok * 40 + d] = __float2half_rn(acc);
            }
        }
    }
    __syncthreads();

    // ---- epilogue: O/lsum + lepe(smem) -> fp16 chunk-major padded g_xh ----
    #pragma unroll
    for (int mt = 0; mt < 2; mt++) {
        const float il = 1.f / lsl[mt];
        const float ih = 1.f / lsh[mt];
        const int lt0 = wid * 32 + mt * 16 + g;          // local token
        const size_t grow = (size_t)w * WIN + z * 256 + lt0;
        #pragma unroll
        for (int ntd = 0; ntd < 4; ntd++) {
            int ch = ntd * 8 + t2;
            float2 e0 = __half22float2(*(const __half2*)(sm + lt0 * 40 + ch));
            float2 e1 = __half22float2(*(const __half2*)(sm + (lt0 + 8) * 40 + ch));
            size_t x0 = (size_t)n * PLANE + grow * 40 + ch;
            size_t x1 = x0 + 8 * 40;
            *(__half2*)(g_xh + x0) = __floats2half2_rn(O[mt][ntd][0] * il + e0.x,
                                                       O[mt][ntd][1] * il + e0.y);
            *(__half2*)(g_xh + x1) = __floats2half2_rn(O[mt][ntd][2] * ih + e1.x,
                                                       O[mt][ntd][3] * ih + e1.y);
        }
    }
}

// ---------------------------------------------------------------------------
// Projection: out = x @ W^T + b. CTA 128m x 128n, 8 warps (4m x 2n) 32x64 tiles.
// cp.async 3-stage pipeline, one sync/chunk, ldmatrix fragments, 2 CTAs/SM.
// A-tile DRAM traffic halved vs 128x64 (each m-block read by 2 CTAs, not 4).
// ---------------------------------------------------------------------------
#define PROJ_STAGE_BYTES (2 * 128 * 40 * 2)              // 20480 (A 10240 + B 10240)
#define PROJ_SMEM_BYTES (3 * PROJ_STAGE_BYTES)           // 61440

__global__ __launch_bounds__(256, 2) void proj_hmma(const float* __restrict__ bias,
                                                    float* __restrict__ out) {
    extern __shared__ __half psm[];
    const int tid = threadIdx.x;
    const int m0 = blockIdx.y * 128, n0 = blockIdx.x * 128;
    const int wid = tid >> 5, lane = tid & 31;
    const int g = lane >> 2, t2 = (lane & 3) * 2;
    const int wm = (wid >> 1) * 32, wn = (wid & 1) * 64;
    const uint32_t sb = smem_u32(psm);

    auto fill = [&](int c) {
        int s = c % 3;
        uint32_t abase = sb + (uint32_t)s * PROJ_STAGE_BYTES;
        const __half* asrc = g_xh + (size_t)c * PLANE + (size_t)m0 * 40;
        #pragma unroll
        for (int i = 0; i < 3; i++) {
            int idx = tid + i * 256;
            if (idx < 640) CP_ASYNC16(abase + idx * 16, asrc + idx * 8);
        }
        uint32_t bbase = abase + 10240u;
        const __half* bsrc = g_wh + (size_t)c * (DIMC * 40) + (size_t)n0 * 40;
        #pragma unroll
        for (int i = 0; i < 3; i++) {
            int idx = tid + i * 256;
            if (idx < 640) CP_ASYNC16(bbase + idx * 16, bsrc + idx * 8);
        }
        CP_COMMIT();
    };

    float D[2][8][4];
    #pragma unroll
    for (int mt = 0; mt < 2; mt++)
        #pragma unroll
        for (int nt = 0; nt < 8; nt++)
            #pragma unroll
            for (int e = 0; e < 4; e++) D[mt][nt][e] = 0.f;

    fill(0); fill(1);

    const uint32_t aoff = (uint32_t)(wm * 80 + (lane & 15) * 80 + (lane >> 4) * 16);
    const uint32_t boff = (uint32_t)(10240 + (wn + (lane & 7)) * 80 + (lane >> 3) * 16);

    #pragma unroll
    for (int c = 0; c < 8; c++) {
        if (c < 7) asm volatile("cp.async.wait_group 1;");
        else       asm volatile("cp.async.wait_group 0;");
        __syncthreads();
        if (c + 2 < 8) fill(c + 2);

        const uint32_t aconst = sb + (uint32_t)(c % 3) * PROJ_STAGE_BYTES + aoff;
        const uint32_t bconst = sb + (uint32_t)(c % 3) * PROJ_STAGE_BYTES + boff;

        uint32_t a[2][2][4];
        #pragma unroll
        for (int mt = 0; mt < 2; mt++)
            #pragma unroll
            for (int ks = 0; ks < 2; ks++)
                LDSM_X4(a[mt][ks][0], a[mt][ks][1], a[mt][ks][2], a[mt][ks][3],
                        aconst + (uint32_t)(mt * 1280 + ks * 32));
        // n processed in two halves of 4 tiles to bound live bb registers
        #pragma unroll
        for (int nh = 0; nh < 2; nh++) {
            uint32_t bb[4][2][2];
            #pragma unroll
            for (int q = 0; q < 4; q++)
                LDSM_X4(bb[q][0][0], bb[q][0][1], bb[q][1][0], bb[q][1][1],
                        bconst + (uint32_t)((nh * 4 + q) * 640));
            #pragma unroll
            for (int mt = 0; mt < 2; mt++)
                #pragma unroll
                for (int q = 0; q < 4; q++)
                    #pragma unroll
                    for (int ks = 0; ks < 2; ks++)
                        mma16816(D[mt][nh * 4 + q], a[mt][ks], bb[q][ks]);
        }
    }

    // ---- scatter epilogue with bias ----
    #pragma unroll
    for (int mt = 0; mt < 2; mt++) {
        #pragma unroll
        for (int nt = 0; nt < 8; nt++) {
            int col = n0 + wn + nt * 8 + t2;
            float2 bv = *(const float2*)&bias[col];
            #pragma unroll
            for (int half = 0; half < 2; half++) {
                int mrow = m0 + wm + mt * 16 + g + half * 8;
                int wI = mrow >> 9, t = mrow & 511;
                int bI = wI >> 3, jI = wI & 7;
                int rI = t >> 3, c2I = t & 7;
                size_t o = ((size_t)bI * LTOK + rI * RESO + jI * 8 + c2I) * DIMC + col;
                float2 r;
                r.x = D[mt][nt][half * 2 + 0] + bv.x;
                r.y = D[mt][nt][half * 2 + 1] + bv.y;
                *(float2*)&out[o] = r;
            }
        }
    }
}

// ---------------------------------------------------------------------------
extern "C" void kernel_launch(void* const* d_in, const int* in_sizes, int n_in,
                              void* d_out, int out_size) {
    (void)in_sizes; (void)n_in; (void)out_size;
    const float* qkv    = (const float*)d_in[0];
    const float* scale  = (const float*)d_in[1];
    const float* proj_w = (const float*)d_in[2];
    const float* proj_b = (const float*)d_in[3];
    const float* conv_w = (const float*)d_in[4];
    const float* conv_b = (const float*)d_in[5];
    float* out = (float*)d_out;

    cudaFuncSetAttribute(attn_hmma, cudaFuncAttributeMaxDynamicSharedMemorySize,
                         ATTN_SMEM_BYTES);
    attn_hmma<<<dim3(2, NWTOT, NH), 256, ATTN_SMEM_BYTES>>>(qkv, scale, conv_w, conv_b,
                                                            proj_w);

    cudaFuncSetAttribute(proj_hmma, cudaFuncAttributeMaxDynamicSharedMemorySize,
                         PROJ_SMEM_BYTES);
    proj_hmma<<<dim3(DIMC / 128, MROWS / 128), 256, PROJ_SMEM_BYTES>>>(proj_b, out);
}